// round 4
// baseline (speedup 1.0000x reference)
#include <cuda_runtime.h>

// StDevLoss: windowed 3D-point-distance std over 7x7 clamped windows.
// depthin: (1,1,480,640) fp32; gt unused; output: scalar fp32.

#define ROWS 480
#define COLS 640
#define S7   7
#define PAD  3

#define BX 32
#define BY 16
#define TW (BX + 6)   // 38
#define TH (BY + 6)   // 22
#define TP 40         // padded shared row stride (floats)

#define GRIDX (COLS / BX)   // 20
#define GRIDY (ROWS / BY)   // 30
#define NPART (GRIDX * GRIDY)

__device__ float g_partials[NPART];

__global__ __launch_bounds__(BX * BY)
void stdev_kernel(const float* __restrict__ depth) {
    const float CXc   = 313.0447587080473f;
    const float CYc   = 238.44389626620386f;
    const float invFX = 1.0f / 582.6244816773795f;
    const float invFY = 1.0f / 582.6910327098864f;

    __shared__ float shx[TH * TP];
    __shared__ float shy[TH * TP];
    __shared__ float shz[TH * TP];
    __shared__ float red[BX * BY];

    const int tx  = threadIdx.x;
    const int ty  = threadIdx.y;
    const int tid = ty * BX + tx;
    const int c0  = blockIdx.x * BX;
    const int r0  = blockIdx.y * BY;

    // Cooperative load of the haloed tile; compute x,y,z once per point.
    // Out-of-image halo cells are clamped (they are provably never read by
    // the clamped-window logic, but must hold finite values).
    for (int i = tid; i < TH * TW; i += BX * BY) {
        const int sr = i / TW;
        const int sc = i % TW;
        int gr = r0 - PAD + sr;
        int gc = c0 - PAD + sc;
        gr = min(max(gr, 0), ROWS - 1);
        gc = min(max(gc, 0), COLS - 1);
        const float d = depth[gr * COLS + gc];
        const bool valid = (d > 0.0f) && (d < 1.01f);
        const float z = valid ? d * 1e-3f : 0.0f;
        const int o = sr * TP + sc;
        shz[o] = z;
        shx[o] = z * ((float)gc - CXc) * invFX;
        shy[o] = z * ((float)gr - CYc) * invFY;
    }
    __syncthreads();

    const int r = r0 + ty;
    const int c = c0 + tx;
    const int o0 = (ty + PAD) * TP + (tx + PAD);
    const float xc = shx[o0];
    const float yc = shy[o0];
    const float zc = shz[o0];

    // Clamped window start, converted to shared-tile coordinates.
    const int ib = min(max(r - PAD, 0), ROWS - S7) - r0 + PAD;
    const int jb = min(max(c - PAD, 0), COLS - S7) - c0 + PAD;

    float s1 = 0.0f;   // sum of distances
    float s2 = 0.0f;   // sum of squared distances

    #pragma unroll
    for (int dy = 0; dy < S7; dy++) {
        const int rowoff = (ib + dy) * TP + jb;
        const float* __restrict__ px = shx + rowoff;
        const float* __restrict__ py = shy + rowoff;
        const float* __restrict__ pz = shz + rowoff;
        #pragma unroll
        for (int dx = 0; dx < S7; dx++) {
            const float ddx = xc - px[dx];
            const float ddy = yc - py[dx];
            const float ddz = zc - pz[dx];
            float ss = ddx * ddx;
            ss = fmaf(ddy, ddy, ss);
            ss = fmaf(ddz, ddz, ss);
            // sqrt(ss) via one MUFU.RSQ; guard exact zero (self-term / all-invalid).
            const float dd = (ss > 0.0f) ? ss * rsqrtf(ss) : 0.0f;
            s1 += dd;
            s2 = fmaf(dd, dd, s2);
        }
    }

    // var = (sum(d^2) - (sum d)^2 / 49) / 48   (Bessel-corrected)
    const float mean = s1 * (1.0f / 49.0f);
    float var = fmaf(-mean, s1, s2) * (1.0f / 48.0f);
    var = fmaxf(var, 0.0f);
    const float dev = (zc > 0.0f) ? sqrtf(var) : 0.0f;

    // Deterministic block reduction.
    red[tid] = dev;
    __syncthreads();
    #pragma unroll
    for (int s = (BX * BY) / 2; s > 0; s >>= 1) {
        if (tid < s) red[tid] += red[tid + s];
        __syncthreads();
    }
    if (tid == 0)
        g_partials[blockIdx.y * GRIDX + blockIdx.x] = red[0];
}

__global__ void finish_kernel(float* __restrict__ out) {
    __shared__ float red[256];
    float s = 0.0f;
    for (int i = threadIdx.x; i < NPART; i += 256)
        s += g_partials[i];
    red[threadIdx.x] = s;
    __syncthreads();
    #pragma unroll
    for (int k = 128; k > 0; k >>= 1) {
        if (threadIdx.x < k) red[threadIdx.x] += red[threadIdx.x + k];
        __syncthreads();
    }
    if (threadIdx.x == 0)
        out[0] = red[0] * 100.0f;
}

extern "C" void kernel_launch(void* const* d_in, const int* in_sizes, int n_in,
                              void* d_out, int out_size) {
    const float* depth = (const float*)d_in[0];
    float* out = (float*)d_out;

    dim3 grid(GRIDX, GRIDY);
    dim3 block(BX, BY);
    stdev_kernel<<<grid, block>>>(depth);
    finish_kernel<<<1, 256>>>(out);
}

// round 5
// speedup vs baseline: 1.1215x; 1.1215x over previous
#include <cuda_runtime.h>

// StDevLoss: 7x7 clamped-window 3D-point-distance std, summed, x100.
// depthin (1,1,480,640) fp32 -> scalar fp32. Single fused kernel.

#define ROWS 480
#define COLS 640

#define BX 32
#define BY 4
#define NT (BX * BY)          // 128 threads
#define PIX_Y 8               // pixel rows per block (2 per thread)
#define TW (BX + 6)           // 38
#define TH (PIX_Y + 6)        // 14
#define TP 40                 // shared row stride

#define GRIDX (COLS / BX)     // 20
#define GRIDY (ROWS / PIX_Y)  // 60
#define NPART (GRIDX * GRIDY) // 1200

__device__ float g_partials[NPART];
__device__ unsigned int g_count = 0;

__device__ __forceinline__ float sqrt_approx(float x) {
    float r;
    asm("sqrt.approx.f32 %0, %1;" : "=f"(r) : "f"(x));
    return r;   // sqrt.approx(0) == 0, so no zero-guard needed
}

__global__ __launch_bounds__(NT)
void stdev_kernel(const float* __restrict__ depth, float* __restrict__ out) {
    const float CXc   = 313.0447587080473f;
    const float CYc   = 238.44389626620386f;
    const float invFX = 1.0f / 582.6244816773795f;
    const float invFY = 1.0f / 582.6910327098864f;

    __shared__ float shz[TH * TP];   // z only; x,y recomputed via FFMA
    __shared__ float red[NT];
    __shared__ unsigned int s_last;

    const int tx  = threadIdx.x;
    const int ty  = threadIdx.y;
    const int tid = ty * BX + tx;
    const int c0  = blockIdx.x * BX;
    const int r0  = blockIdx.y * PIX_Y;

    // Cooperative haloed z-tile load (clamped; clamped halo never read by
    // the clamped-window indexing but must be finite).
    for (int i = tid; i < TH * TW; i += NT) {
        const int sr = i / TW;
        const int sc = i - sr * TW;
        const int gr = min(max(r0 - 3 + sr, 0), ROWS - 1);
        const int gc = min(max(c0 - 3 + sc, 0), COLS - 1);
        const float d = depth[gr * COLS + gc];
        shz[sr * TP + sc] = (d > 0.0f && d < 1.01f) ? d * 1e-3f : 0.0f;
    }
    __syncthreads();

    // Per-thread column factors (same for both pixels in the column).
    const int c    = c0 + tx;
    const int jb   = min(max(c - 3, 0), COLS - 7);
    const int jb_s = jb - c0 + 3;
    float ncf[7];
    #pragma unroll
    for (int j = 0; j < 7; j++)
        ncf[j] = -((float)(jb + j) - CXc) * invFX;
    const float cfc = ((float)c - CXc) * invFX;

    float total = 0.0f;

    #pragma unroll
    for (int p = 0; p < 2; p++) {
        const int r    = r0 + ty + p * BY;
        const int ib   = min(max(r - 3, 0), ROWS - 7);
        const int ib_s = ib - r0 + 3;

        const float zc = shz[(ty + p * BY + 3) * TP + (tx + 3)];
        const float xc = zc * cfc;
        const float yc = zc * (((float)r - CYc) * invFY);

        float s1 = 0.0f;   // sum d
        float s2 = 0.0f;   // sum d^2 (= sum ss, no sqrt needed)

        #pragma unroll
        for (int i = 0; i < 7; i++) {
            const float nrf = -((float)(ib + i) - CYc) * invFY;
            const float* __restrict__ rowp = &shz[(ib_s + i) * TP + jb_s];
            #pragma unroll
            for (int j = 0; j < 7; j++) {
                const float zn  = rowp[j];
                const float ddx = fmaf(zn, ncf[j], xc);   // xc - zn*cf[j]
                const float ddy = fmaf(zn, nrf, yc);      // yc - zn*rf[i]
                const float ddz = zc - zn;
                float ss = ddx * ddx;
                ss = fmaf(ddy, ddy, ss);
                ss = fmaf(ddz, ddz, ss);
                s2 += ss;
                s1 += sqrt_approx(ss);
            }
        }

        // var = (sum d^2 - (sum d)^2/49) / 48  (Bessel-corrected)
        const float mean = s1 * (1.0f / 49.0f);
        float var = fmaf(-mean, s1, s2) * (1.0f / 48.0f);
        var = fmaxf(var, 0.0f);
        total += (zc > 0.0f) ? sqrt_approx(var) : 0.0f;
    }

    // Deterministic block reduction.
    red[tid] = total;
    __syncthreads();
    #pragma unroll
    for (int s = NT / 2; s > 0; s >>= 1) {
        if (tid < s) red[tid] += red[tid + s];
        __syncthreads();
    }

    // Fused final reduction: last block to arrive sums all partials in
    // fixed index order (deterministic), writes out, resets the counter.
    if (tid == 0) {
        g_partials[blockIdx.y * GRIDX + blockIdx.x] = red[0];
        __threadfence();
        const unsigned int t = atomicAdd(&g_count, 1u);
        s_last = (t == NPART - 1) ? 1u : 0u;
    }
    __syncthreads();

    if (s_last) {
        const volatile float* vp = g_partials;
        float s = 0.0f;
        for (int i = tid; i < NPART; i += NT) s += vp[i];
        red[tid] = s;
        __syncthreads();
        #pragma unroll
        for (int k = NT / 2; k > 0; k >>= 1) {
            if (tid < k) red[tid] += red[tid + k];
            __syncthreads();
        }
        if (tid == 0) {
            out[0] = red[0] * 100.0f;
            g_count = 0;   // re-arm for next graph replay
        }
    }
}

extern "C" void kernel_launch(void* const* d_in, const int* in_sizes, int n_in,
                              void* d_out, int out_size) {
    const float* depth = (const float*)d_in[0];
    float* out = (float*)d_out;

    dim3 grid(GRIDX, GRIDY);
    dim3 block(BX, BY);
    stdev_kernel<<<grid, block>>>(depth, out);
}